// round 3
// baseline (speedup 1.0000x reference)
#include <cuda_runtime.h>
#include <math.h>

#define DV     256
#define HIDV   512
#define O_MAX  50000
#define E_MAX  200000
#define CONSTV 10.0f

// ---------------- static device scratch ----------------
__device__ float g_W1p[256 * 1024];             // repacked W1: [256,1024]  (top|bot)
__device__ float g_W2p[1024 * 256];             // repacked W2: [1024,256]  (left;right)
__device__ float g_P[(size_t)O_MAX * 1024];     // X@W1' : [O,1024]
__device__ float g_H[(size_t)O_MAX * 1024];     // [Σ w h | Σ w h] : [O,1024]
__device__ float g_m[O_MAX];                    // max(conf, CONST) per node
__device__ float g_Ws[O_MAX];
__device__ float g_Wo[O_MAX];
__device__ int   g_pairs[2 * E_MAX];
__device__ int   g_is64;
__device__ int   g_cnt[O_MAX];                  // incidence counts
__device__ int   g_off[O_MAX + 1];              // CSR offsets
__device__ int   g_cur[O_MAX];                  // fill cursors
__device__ int   g_items[2 * E_MAX];            // packed (e<<1)|role

// ---------------- f32x2 helpers ----------------
__device__ __forceinline__ void ffma2(unsigned long long& d, unsigned long long a,
                                      unsigned long long b) {
    asm volatile("fma.rn.f32x2 %0, %1, %2, %0;" : "+l"(d) : "l"(a), "l"(b));
}
__device__ __forceinline__ unsigned long long pack2(float x, float y) {
    unsigned long long r;
    asm("mov.b64 %0, {%1, %2};" : "=l"(r) : "f"(x), "f"(y));
    return r;
}
__device__ __forceinline__ void unpack2(float& x, float& y, unsigned long long v) {
    asm("mov.b64 {%0, %1}, %2;" : "=f"(x), "=f"(y) : "l"(v));
}

// ---------------- setup kernels ----------------

// pairs dtype detect: int64 node ids < 50000 -> every odd 32-bit word is 0.
__global__ void detect_kernel(const int* __restrict__ p) {
    if (threadIdx.x == 0 && blockIdx.x == 0) {
        int all0 = 1;
        for (int i = 1; i < 129; i += 2)
            if (p[i] != 0) { all0 = 0; break; }
        g_is64 = all0;
    }
}

__global__ void convert_pairs_kernel(const int* __restrict__ p, int n2) {
    int i = blockIdx.x * blockDim.x + threadIdx.x;
    if (i >= n2) return;
    g_pairs[i] = g_is64 ? p[2 * i] : p[i];
}

__global__ void repack_kernel(const float* __restrict__ W1, const float* __restrict__ W2) {
    int i = blockIdx.x * blockDim.x + threadIdx.x;
    if (i < 256 * 1024) {
        int k = i >> 10, j = i & 1023;
        g_W1p[i] = (j < 512) ? W1[k * 512 + j] : W1[(k + 256) * 512 + (j - 512)];
    }
    if (i < 1024 * 256) {
        int k = i >> 8, j = i & 255;
        g_W2p[i] = (k < 512) ? W2[k * 512 + j] : W2[(k - 512) * 512 + (j + 256)];
    }
}

__global__ void init_kernel(int O) {
    for (int i = blockIdx.x * blockDim.x + threadIdx.x; i < O; i += gridDim.x * blockDim.x) {
        g_m[i] = CONSTV;
        g_cnt[i] = 0;
    }
}

// seg-max of conf into g_m + incidence counting
__global__ void edge_max_count_kernel(const float* __restrict__ conf, int E) {
    int e = blockIdx.x * blockDim.x + threadIdx.x;
    if (e >= E) return;
    int s = g_pairs[2 * e], o = g_pairs[2 * e + 1];
    float c = conf[e];
    if (c > CONSTV) {   // g_m init = CONSTV > 0, float-as-int atomicMax valid for positives
        atomicMax((int*)&g_m[s], __float_as_int(c));
        atomicMax((int*)&g_m[o], __float_as_int(c));
    }
    atomicAdd(&g_cnt[s], 1);
    atomicAdd(&g_cnt[o], 1);
}

// single-block Hillis-Steele scan over counts -> exclusive offsets + cursors
__global__ void scan_kernel(int O) {
    __shared__ int sm[1024];
    __shared__ int s_carry;
    int tid = threadIdx.x;
    if (tid == 0) s_carry = 0;
    __syncthreads();
    for (int base = 0; base < O; base += 1024) {
        int i = base + tid;
        int v = (i < O) ? g_cnt[i] : 0;
        sm[tid] = v;
        __syncthreads();
        for (int d = 1; d < 1024; d <<= 1) {
            int t = (tid >= d) ? sm[tid - d] : 0;
            __syncthreads();
            sm[tid] += t;
            __syncthreads();
        }
        int excl = s_carry + sm[tid] - v;
        if (i < O) { g_off[i] = excl; g_cur[i] = excl; }
        __syncthreads();
        if (tid == 1023) s_carry += sm[1023];
        __syncthreads();
    }
    if (tid == 0) g_off[O] = s_carry;
}

__global__ void fill_kernel(int E) {
    int e = blockIdx.x * blockDim.x + threadIdx.x;
    if (e >= E) return;
    int s = g_pairs[2 * e], o = g_pairs[2 * e + 1];
    g_items[atomicAdd(&g_cur[s], 1)] = (e << 1);
    g_items[atomicAdd(&g_cur[o], 1)] = (e << 1) | 1;
}

// ---------------- SGEMM (f32x2 packed), 128x128x16, 256 threads, 8x8/thread ----------------
// EPI==0: plain store. EPI==1: fused BGConv epilogue.
template <int EPI>
__global__ void sgemm_kernel(const float* __restrict__ A, const float* __restrict__ Bm,
                             float* __restrict__ C, int M, int N, int K,
                             const float* __restrict__ X, const float* __restrict__ b2) {
    const int BM = 128, BN = 128, BK = 16, TM = 8;
    __shared__ float As[BK][BM + 4];
    __shared__ float Bs[BK][BN];
    int tid = threadIdx.x;
    int tx = tid & 15, ty = tid >> 4;
    int bm0 = blockIdx.y * BM, bn0 = blockIdx.x * BN;

    unsigned long long acc2[TM][4];   // 8 rows x 4 col-pairs
#pragma unroll
    for (int i = 0; i < TM; i++)
#pragma unroll
        for (int j = 0; j < 4; j++) acc2[i][j] = 0ULL;

    for (int k0 = 0; k0 < K; k0 += BK) {
#pragma unroll
        for (int l = 0; l < 2; l++) {
            int f  = tid + l * 256;
            int ar = f >> 2;
            int ac = (f & 3) * 4;
            float4 v = make_float4(0.f, 0.f, 0.f, 0.f);
            int grow = bm0 + ar;
            if (grow < M)
                v = *reinterpret_cast<const float4*>(A + (size_t)grow * K + k0 + ac);
            As[ac + 0][ar] = v.x; As[ac + 1][ar] = v.y;
            As[ac + 2][ar] = v.z; As[ac + 3][ar] = v.w;
        }
#pragma unroll
        for (int l = 0; l < 2; l++) {
            int f  = tid + l * 256;
            int br = f >> 5;
            int bc = (f & 31) * 4;
            *reinterpret_cast<float4*>(&Bs[br][bc]) =
                *reinterpret_cast<const float4*>(Bm + (size_t)(k0 + br) * N + bn0 + bc);
        }
        __syncthreads();
#pragma unroll
        for (int k = 0; k < BK; k++) {
            float4 a0 = *reinterpret_cast<const float4*>(&As[k][ty * TM]);
            float4 a1 = *reinterpret_cast<const float4*>(&As[k][ty * TM + 4]);
            unsigned long long ap[8];
            ap[0] = pack2(a0.x, a0.x); ap[1] = pack2(a0.y, a0.y);
            ap[2] = pack2(a0.z, a0.z); ap[3] = pack2(a0.w, a0.w);
            ap[4] = pack2(a1.x, a1.x); ap[5] = pack2(a1.y, a1.y);
            ap[6] = pack2(a1.z, a1.z); ap[7] = pack2(a1.w, a1.w);
            const unsigned long long* B64 =
                reinterpret_cast<const unsigned long long*>(&Bs[k][tx * 8]);
            unsigned long long bp0 = B64[0], bp1 = B64[1], bp2 = B64[2], bp3 = B64[3];
#pragma unroll
            for (int i = 0; i < TM; i++) {
                ffma2(acc2[i][0], ap[i], bp0);
                ffma2(acc2[i][1], ap[i], bp1);
                ffma2(acc2[i][2], ap[i], bp2);
                ffma2(acc2[i][3], ap[i], bp3);
            }
        }
        __syncthreads();
    }

#pragma unroll
    for (int i = 0; i < TM; i++) {
        int row = bm0 + ty * TM + i;
        if (row >= M) continue;
        float ws = 0.f, wo = 0.f, sw = 0.f, inv = 1.f;
        if (EPI == 1) {
            ws = g_Ws[row]; wo = g_Wo[row];
            sw = expf(CONSTV - g_m[row]);
            inv = 1.f / (ws + wo + sw);
        }
#pragma unroll
        for (int j = 0; j < 4; j++) {
            float lo, hi;
            unpack2(lo, hi, acc2[i][j]);
            int col = bn0 + tx * 8 + 2 * j;
            if (EPI == 0) {
                C[(size_t)row * N + col]     = lo;
                C[(size_t)row * N + col + 1] = hi;
            } else {
                float v0 = lo + ws * b2[col]     + wo * b2[col + DV]
                           + sw * X[(size_t)row * DV + col];
                float v1 = hi + ws * b2[col + 1] + wo * b2[col + 1 + DV]
                           + sw * X[(size_t)row * DV + col + 1];
                C[(size_t)row * N + col]     = v0 * inv;
                C[(size_t)row * N + col + 1] = v1 * inv;
            }
        }
    }
}

// ---------------- node-centric accumulation (no atomics) ----------------
// One warp per node. Registers hold P[n,:] halves, b1, and both 512-wide accumulators.
__global__ void node_kernel(const float* __restrict__ conf, const float* __restrict__ b1,
                            int O) {
    int n    = (blockIdx.x * blockDim.x + threadIdx.x) >> 5;
    int lane = threadIdx.x & 31;
    if (n >= O) return;

    const float4* Pn = reinterpret_cast<const float4*>(g_P + (size_t)n * 1024);
    const float4* B1 = reinterpret_cast<const float4*>(b1);
    float4 ps0[4], ps1[4], bv[4], acc0[4], acc1[4];
#pragma unroll
    for (int j = 0; j < 4; j++) {
        int idx = lane + j * 32;
        ps0[j] = Pn[idx];
        ps1[j] = Pn[128 + idx];
        bv[j]  = B1[idx];
        acc0[j] = make_float4(0.f, 0.f, 0.f, 0.f);
        acc1[j] = make_float4(0.f, 0.f, 0.f, 0.f);
    }
    float wssum = 0.f, wosum = 0.f;
    float mn = g_m[n];
    int beg = g_off[n], end = g_off[n + 1];

    for (int it = beg; it < end; ++it) {
        int item = g_items[it];
        int e = item >> 1, role = item & 1;
        float w = expf(conf[e] - mn);
        int other = g_pairs[2 * e + (role ^ 1)];
        const float4* Po = reinterpret_cast<const float4*>(g_P + (size_t)other * 1024);
        if (role == 0) {        // n is sub: h = relu(P[n,0:512] + P[other,512:] + b1)
            wssum += w;
#pragma unroll
            for (int j = 0; j < 4; j++) {
                int idx = lane + j * 32;
                float4 q = Po[128 + idx];
                float hx = fmaxf(ps0[j].x + q.x + bv[j].x, 0.f);
                float hy = fmaxf(ps0[j].y + q.y + bv[j].y, 0.f);
                float hz = fmaxf(ps0[j].z + q.z + bv[j].z, 0.f);
                float hw = fmaxf(ps0[j].w + q.w + bv[j].w, 0.f);
                acc0[j].x = fmaf(w, hx, acc0[j].x);
                acc0[j].y = fmaf(w, hy, acc0[j].y);
                acc0[j].z = fmaf(w, hz, acc0[j].z);
                acc0[j].w = fmaf(w, hw, acc0[j].w);
            }
        } else {                // n is obj: h = relu(P[other,0:512] + P[n,512:] + b1)
            wosum += w;
#pragma unroll
            for (int j = 0; j < 4; j++) {
                int idx = lane + j * 32;
                float4 q = Po[idx];
                float hx = fmaxf(q.x + ps1[j].x + bv[j].x, 0.f);
                float hy = fmaxf(q.y + ps1[j].y + bv[j].y, 0.f);
                float hz = fmaxf(q.z + ps1[j].z + bv[j].z, 0.f);
                float hw = fmaxf(q.w + ps1[j].w + bv[j].w, 0.f);
                acc1[j].x = fmaf(w, hx, acc1[j].x);
                acc1[j].y = fmaf(w, hy, acc1[j].y);
                acc1[j].z = fmaf(w, hz, acc1[j].z);
                acc1[j].w = fmaf(w, hw, acc1[j].w);
            }
        }
    }

    float4* Hn = reinterpret_cast<float4*>(g_H + (size_t)n * 1024);
#pragma unroll
    for (int j = 0; j < 4; j++) {
        int idx = lane + j * 32;
        Hn[idx]       = acc0[j];
        Hn[128 + idx] = acc1[j];
    }
    if (lane == 0) { g_Ws[n] = wssum; g_Wo[n] = wosum; }
}

// ---------------- launch ----------------
extern "C" void kernel_launch(void* const* d_in, const int* in_sizes, int n_in,
                              void* d_out, int out_size) {
    const float* X     = (const float*)d_in[0];
    const int*   pairs = (const int*)d_in[1];
    const float* conf  = (const float*)d_in[2];
    const float* W1    = (const float*)d_in[3];
    const float* b1    = (const float*)d_in[4];
    const float* W2    = (const float*)d_in[5];
    const float* b2    = (const float*)d_in[6];
    float*       out   = (float*)d_out;

    int O = in_sizes[0] / DV;
    int E = in_sizes[2];

    detect_kernel<<<1, 32>>>(pairs);
    convert_pairs_kernel<<<(2 * E + 255) / 256, 256>>>(pairs, 2 * E);
    repack_kernel<<<1024, 256>>>(W1, W2);
    init_kernel<<<256, 256>>>(O);
    edge_max_count_kernel<<<(E + 255) / 256, 256>>>(conf, E);
    scan_kernel<<<1, 1024>>>(O);
    fill_kernel<<<(E + 255) / 256, 256>>>(E);

    // P[O,1024] = X[O,256] @ W1p[256,1024]
    {
        dim3 grid(1024 / 128, (O + 127) / 128);
        sgemm_kernel<0><<<grid, 256>>>(X, g_W1p, g_P, O, 1024, 256, nullptr, nullptr);
    }

    node_kernel<<<(O + 7) / 8, 256>>>(conf, b1, O);

    // out[O,256] = (H @ W2p + bias/self) / denom
    {
        dim3 grid(256 / 128, (O + 127) / 128);
        sgemm_kernel<1><<<grid, 256>>>(g_H, g_W2p, out, O, 256, 1024, X, b2);
    }
}

// round 4
// speedup vs baseline: 1.0133x; 1.0133x over previous
#include <cuda_runtime.h>
#include <math.h>

#define DV     256
#define HIDV   512
#define O_MAX  50000
#define E_MAX  200000
#define CONSTV 10.0f

// ---------------- static device scratch ----------------
__device__ float g_W1p[256 * 1024];             // repacked W1: [256,1024]  (top|bot)
__device__ float g_W2p[1024 * 256];             // repacked W2: [1024,256]  (left;right)
__device__ float g_P[(size_t)O_MAX * 1024];     // X@W1' : [O,1024]
__device__ float g_H[(size_t)O_MAX * 1024];     // [Σ w h | Σ w h] : [O,1024]
__device__ float g_m[O_MAX];                    // max(conf, CONST) per node
__device__ float g_Ws[O_MAX];
__device__ float g_Wo[O_MAX];
__device__ int   g_pairs[2 * E_MAX];
__device__ int   g_is64;
__device__ int   g_cnt[O_MAX];                  // incidence counts
__device__ int   g_off[O_MAX + 1];              // CSR offsets
__device__ int   g_cur[O_MAX];                  // fill cursors
__device__ int2  g_items[2 * E_MAX];            // {(other<<1)|role, conf_bits}

// ---------------- f32x2 helpers ----------------
__device__ __forceinline__ void ffma2(unsigned long long& d, unsigned long long a,
                                      unsigned long long b) {
    asm volatile("fma.rn.f32x2 %0, %1, %2, %0;" : "+l"(d) : "l"(a), "l"(b));
}
__device__ __forceinline__ unsigned long long pack2(float x, float y) {
    unsigned long long r;
    asm("mov.b64 %0, {%1, %2};" : "=l"(r) : "f"(x), "f"(y));
    return r;
}
__device__ __forceinline__ void unpack2(float& x, float& y, unsigned long long v) {
    asm("mov.b64 {%0, %1}, %2;" : "=f"(x), "=f"(y) : "l"(v));
}

// ---------------- setup kernels ----------------

__global__ void detect_kernel(const int* __restrict__ p) {
    if (threadIdx.x == 0 && blockIdx.x == 0) {
        int all0 = 1;
        for (int i = 1; i < 129; i += 2)
            if (p[i] != 0) { all0 = 0; break; }
        g_is64 = all0;
    }
}

__global__ void convert_pairs_kernel(const int* __restrict__ p, int n2) {
    int i = blockIdx.x * blockDim.x + threadIdx.x;
    if (i >= n2) return;
    g_pairs[i] = g_is64 ? p[2 * i] : p[i];
}

__global__ void repack_kernel(const float* __restrict__ W1, const float* __restrict__ W2) {
    int i = blockIdx.x * blockDim.x + threadIdx.x;
    if (i < 256 * 1024) {
        int k = i >> 10, j = i & 1023;
        g_W1p[i] = (j < 512) ? W1[k * 512 + j] : W1[(k + 256) * 512 + (j - 512)];
    }
    if (i < 1024 * 256) {
        int k = i >> 8, j = i & 255;
        g_W2p[i] = (k < 512) ? W2[k * 512 + j] : W2[(k - 512) * 512 + (j + 256)];
    }
}

__global__ void init_kernel(int O) {
    for (int i = blockIdx.x * blockDim.x + threadIdx.x; i < O; i += gridDim.x * blockDim.x) {
        g_m[i] = CONSTV;
        g_cnt[i] = 0;
    }
}

__global__ void edge_max_count_kernel(const float* __restrict__ conf, int E) {
    int e = blockIdx.x * blockDim.x + threadIdx.x;
    if (e >= E) return;
    int s = g_pairs[2 * e], o = g_pairs[2 * e + 1];
    float c = conf[e];
    if (c > CONSTV) {
        atomicMax((int*)&g_m[s], __float_as_int(c));
        atomicMax((int*)&g_m[o], __float_as_int(c));
    }
    atomicAdd(&g_cnt[s], 1);
    atomicAdd(&g_cnt[o], 1);
}

// single-block scan via warp shuffles: 1024 threads, 32 warps
__global__ void scan_kernel(int O) {
    __shared__ int warp_sums[32];
    __shared__ int s_carry;
    int tid = threadIdx.x, lane = tid & 31, wid = tid >> 5;
    if (tid == 0) s_carry = 0;
    __syncthreads();
    for (int base = 0; base < O; base += 1024) {
        int i = base + tid;
        int v = (i < O) ? g_cnt[i] : 0;
        // inclusive warp scan
        int x = v;
#pragma unroll
        for (int d = 1; d < 32; d <<= 1) {
            int t = __shfl_up_sync(0xffffffffu, x, d);
            if (lane >= d) x += t;
        }
        if (lane == 31) warp_sums[wid] = x;
        __syncthreads();
        if (wid == 0) {
            int y = warp_sums[lane];
#pragma unroll
            for (int d = 1; d < 32; d <<= 1) {
                int t = __shfl_up_sync(0xffffffffu, y, d);
                if (lane >= d) y += t;
            }
            warp_sums[lane] = y;
        }
        __syncthreads();
        int incl = x + (wid ? warp_sums[wid - 1] : 0);
        int excl = s_carry + incl - v;
        if (i < O) { g_off[i] = excl; g_cur[i] = excl; }
        __syncthreads();
        if (tid == 1023) s_carry += incl;
        __syncthreads();
    }
    if (tid == 0) g_off[O] = s_carry;
}

// store fully-resolved records so the node loop has a 2-level dependency chain
__global__ void fill_kernel(const float* __restrict__ conf, int E) {
    int e = blockIdx.x * blockDim.x + threadIdx.x;
    if (e >= E) return;
    int s = g_pairs[2 * e], o = g_pairs[2 * e + 1];
    int cb = __float_as_int(conf[e]);
    g_items[atomicAdd(&g_cur[s], 1)] = make_int2((o << 1) | 0, cb);  // n=s is sub, other=o
    g_items[atomicAdd(&g_cur[o], 1)] = make_int2((s << 1) | 1, cb);  // n=o is obj, other=s
}

// ---------------- SGEMM (f32x2 packed), 128x128x16, 256 threads, 8x8/thread ----------------
template <int EPI>
__global__ void sgemm_kernel(const float* __restrict__ A, const float* __restrict__ Bm,
                             float* __restrict__ C, int M, int N, int K,
                             const float* __restrict__ X, const float* __restrict__ b2) {
    const int BM = 128, BN = 128, BK = 16, TM = 8;
    __shared__ float As[BK][BM + 4];
    __shared__ float Bs[BK][BN];
    int tid = threadIdx.x;
    int tx = tid & 15, ty = tid >> 4;
    int bm0 = blockIdx.y * BM, bn0 = blockIdx.x * BN;

    unsigned long long acc2[TM][4];
#pragma unroll
    for (int i = 0; i < TM; i++)
#pragma unroll
        for (int j = 0; j < 4; j++) acc2[i][j] = 0ULL;

    for (int k0 = 0; k0 < K; k0 += BK) {
#pragma unroll
        for (int l = 0; l < 2; l++) {
            int f  = tid + l * 256;
            int ar = f >> 2;
            int ac = (f & 3) * 4;
            float4 v = make_float4(0.f, 0.f, 0.f, 0.f);
            int grow = bm0 + ar;
            if (grow < M)
                v = *reinterpret_cast<const float4*>(A + (size_t)grow * K + k0 + ac);
            As[ac + 0][ar] = v.x; As[ac + 1][ar] = v.y;
            As[ac + 2][ar] = v.z; As[ac + 3][ar] = v.w;
        }
#pragma unroll
        for (int l = 0; l < 2; l++) {
            int f  = tid + l * 256;
            int br = f >> 5;
            int bc = (f & 31) * 4;
            *reinterpret_cast<float4*>(&Bs[br][bc]) =
                *reinterpret_cast<const float4*>(Bm + (size_t)(k0 + br) * N + bn0 + bc);
        }
        __syncthreads();
#pragma unroll
        for (int k = 0; k < BK; k++) {
            float4 a0 = *reinterpret_cast<const float4*>(&As[k][ty * TM]);
            float4 a1 = *reinterpret_cast<const float4*>(&As[k][ty * TM + 4]);
            unsigned long long ap[8];
            ap[0] = pack2(a0.x, a0.x); ap[1] = pack2(a0.y, a0.y);
            ap[2] = pack2(a0.z, a0.z); ap[3] = pack2(a0.w, a0.w);
            ap[4] = pack2(a1.x, a1.x); ap[5] = pack2(a1.y, a1.y);
            ap[6] = pack2(a1.z, a1.z); ap[7] = pack2(a1.w, a1.w);
            const unsigned long long* B64 =
                reinterpret_cast<const unsigned long long*>(&Bs[k][tx * 8]);
            unsigned long long bp0 = B64[0], bp1 = B64[1], bp2 = B64[2], bp3 = B64[3];
#pragma unroll
            for (int i = 0; i < TM; i++) {
                ffma2(acc2[i][0], ap[i], bp0);
                ffma2(acc2[i][1], ap[i], bp1);
                ffma2(acc2[i][2], ap[i], bp2);
                ffma2(acc2[i][3], ap[i], bp3);
            }
        }
        __syncthreads();
    }

#pragma unroll
    for (int i = 0; i < TM; i++) {
        int row = bm0 + ty * TM + i;
        if (row >= M) continue;
        float ws = 0.f, wo = 0.f, sw = 0.f, inv = 1.f;
        if (EPI == 1) {
            ws = g_Ws[row]; wo = g_Wo[row];
            sw = expf(CONSTV - g_m[row]);
            inv = 1.f / (ws + wo + sw);
        }
#pragma unroll
        for (int j = 0; j < 4; j++) {
            float lo, hi;
            unpack2(lo, hi, acc2[i][j]);
            int col = bn0 + tx * 8 + 2 * j;
            if (EPI == 0) {
                C[(size_t)row * N + col]     = lo;
                C[(size_t)row * N + col + 1] = hi;
            } else {
                float v0 = lo + ws * b2[col]     + wo * b2[col + DV]
                           + sw * X[(size_t)row * DV + col];
                float v1 = hi + ws * b2[col + 1] + wo * b2[col + 1 + DV]
                           + sw * X[(size_t)row * DV + col + 1];
                C[(size_t)row * N + col]     = v0 * inv;
                C[(size_t)row * N + col + 1] = v1 * inv;
            }
        }
    }
}

// ---------------- node-centric accumulation (no atomics, 2-level chain) ----------------
__global__ void node_kernel(const float* __restrict__ b1, int O) {
    int n    = (blockIdx.x * blockDim.x + threadIdx.x) >> 5;
    int lane = threadIdx.x & 31;
    if (n >= O) return;

    const float4* Pn = reinterpret_cast<const float4*>(g_P + (size_t)n * 1024);
    const float4* B1 = reinterpret_cast<const float4*>(b1);
    float4 ps0[4], ps1[4], bv[4], acc0[4], acc1[4];
#pragma unroll
    for (int j = 0; j < 4; j++) {
        int idx = lane + j * 32;
        ps0[j] = Pn[idx];
        ps1[j] = Pn[128 + idx];
        bv[j]  = B1[idx];
        acc0[j] = make_float4(0.f, 0.f, 0.f, 0.f);
        acc1[j] = make_float4(0.f, 0.f, 0.f, 0.f);
    }
    float wssum = 0.f, wosum = 0.f;
    float mn = g_m[n];
    int beg = g_off[n], end = g_off[n + 1];

    int2 rec = (beg < end) ? g_items[beg] : make_int2(0, 0);
    for (int it = beg; it < end; ++it) {
        int2 next = (it + 1 < end) ? g_items[it + 1] : make_int2(0, 0);
        int other = rec.x >> 1, role = rec.x & 1;
        float w = expf(__int_as_float(rec.y) - mn);
        const float4* Po = reinterpret_cast<const float4*>(g_P + (size_t)other * 1024);
        if (role == 0) {
            wssum += w;
#pragma unroll
            for (int j = 0; j < 4; j++) {
                int idx = lane + j * 32;
                float4 q = Po[128 + idx];
                float hx = fmaxf(ps0[j].x + q.x + bv[j].x, 0.f);
                float hy = fmaxf(ps0[j].y + q.y + bv[j].y, 0.f);
                float hz = fmaxf(ps0[j].z + q.z + bv[j].z, 0.f);
                float hw = fmaxf(ps0[j].w + q.w + bv[j].w, 0.f);
                acc0[j].x = fmaf(w, hx, acc0[j].x);
                acc0[j].y = fmaf(w, hy, acc0[j].y);
                acc0[j].z = fmaf(w, hz, acc0[j].z);
                acc0[j].w = fmaf(w, hw, acc0[j].w);
            }
        } else {
            wosum += w;
#pragma unroll
            for (int j = 0; j < 4; j++) {
                int idx = lane + j * 32;
                float4 q = Po[idx];
                float hx = fmaxf(q.x + ps1[j].x + bv[j].x, 0.f);
                float hy = fmaxf(q.y + ps1[j].y + bv[j].y, 0.f);
                float hz = fmaxf(q.z + ps1[j].z + bv[j].z, 0.f);
                float hw = fmaxf(q.w + ps1[j].w + bv[j].w, 0.f);
                acc1[j].x = fmaf(w, hx, acc1[j].x);
                acc1[j].y = fmaf(w, hy, acc1[j].y);
                acc1[j].z = fmaf(w, hz, acc1[j].z);
                acc1[j].w = fmaf(w, hw, acc1[j].w);
            }
        }
        rec = next;
    }

    float4* Hn = reinterpret_cast<float4*>(g_H + (size_t)n * 1024);
#pragma unroll
    for (int j = 0; j < 4; j++) {
        int idx = lane + j * 32;
        Hn[idx]       = acc0[j];
        Hn[128 + idx] = acc1[j];
    }
    if (lane == 0) { g_Ws[n] = wssum; g_Wo[n] = wosum; }
}

// ---------------- launch ----------------
extern "C" void kernel_launch(void* const* d_in, const int* in_sizes, int n_in,
                              void* d_out, int out_size) {
    const float* X     = (const float*)d_in[0];
    const int*   pairs = (const int*)d_in[1];
    const float* conf  = (const float*)d_in[2];
    const float* W1    = (const float*)d_in[3];
    const float* b1    = (const float*)d_in[4];
    const float* W2    = (const float*)d_in[5];
    const float* b2    = (const float*)d_in[6];
    float*       out   = (float*)d_out;

    int O = in_sizes[0] / DV;
    int E = in_sizes[2];

    // Launch order arranged so the ncu capture window (empirically the 4th
    // launch of the process) lands on sgemm_kernel<0> — GEMM1, the main suspect.
    detect_kernel<<<1, 32>>>(pairs);                               // 1
    convert_pairs_kernel<<<(2 * E + 255) / 256, 256>>>(pairs, 2 * E); // 2
    repack_kernel<<<1024, 256>>>(W1, W2);                          // 3
    {                                                              // 4  <-- captured
        dim3 grid(1024 / 128, (O + 127) / 128);
        sgemm_kernel<0><<<grid, 256>>>(X, g_W1p, g_P, O, 1024, 256, nullptr, nullptr);
    }
    init_kernel<<<256, 256>>>(O);                                  // 5
    edge_max_count_kernel<<<(E + 255) / 256, 256>>>(conf, E);      // 6
    scan_kernel<<<1, 1024>>>(O);                                   // 7
    fill_kernel<<<(E + 255) / 256, 256>>>(conf, E);                // 8
    node_kernel<<<(O + 7) / 8, 256>>>(b1, O);                      // 9
    {                                                              // 10
        dim3 grid(256 / 128, (O + 127) / 128);
        sgemm_kernel<1><<<grid, 256>>>(g_H, g_W2p, out, O, 256, 1024, X, b2);
    }
}